// round 16
// baseline (speedup 1.0000x reference)
#include <cuda_runtime.h>
#include <cuda_fp16.h>
#include <math.h>
#include <stdint.h>

#define D_    1024
#define A_    64
#define TOPK_ 32
#define B_    2
#define S_    4096
#define N_    (B_ * S_)
#define DI_   4096

typedef __half fp16;

// ---------------------------------------------------------------------------
// Device-global scratch
// ---------------------------------------------------------------------------
__device__ __align__(256) float g_vr[2 * N_ * D_];          // v then r
__device__ __align__(256) float g_Vsa[N_ * D_];
__device__ __align__(256) float g_scores[(long long)B_ * S_ * S_];
__device__ __align__(256) float g_xmid[N_ * D_];
__device__ __align__(256) float g_r2[N_ * D_];
__device__ __align__(256) float g_bias[1152];

__device__ __align__(256) fp16 g_x1h[N_ * D_],  g_x1l[N_ * D_];
__device__ __align__(256) fp16 g_xabh[2 * N_ * D_], g_xabl[2 * N_ * D_];   // xa | xb
__device__ __align__(256) fp16 g_qkh[N_ * 128], g_qkl[N_ * 128];
__device__ __align__(256) fp16 g_aph[N_ * D_],  g_apl[N_ * D_];
__device__ __align__(256) fp16 g_rkh[N_ * D_],  g_rkl[N_ * D_];
__device__ __align__(256) fp16 g_kch[(long long)N_ * DI_], g_kcl[(long long)N_ * DI_];

// hi/lo fp16 weights
__device__ __align__(256) fp16 g_wvrh[2 * D_ * D_],  g_wvrl[2 * D_ * D_];
__device__ __align__(256) fp16 g_wqksvh[1152 * D_],  g_wqksvl[1152 * D_];
__device__ __align__(256) fp16 g_woh[D_ * D_],   g_wol[D_ * D_];
__device__ __align__(256) fp16 g_wtoh[D_ * D_],  g_wtol[D_ * D_];
__device__ __align__(256) fp16 g_wckcrh[5120 * D_], g_wckcrl[5120 * D_];   // [ck;cr]
__device__ __align__(256) fp16 g_wcvh[(long long)D_ * DI_], g_wcvl[(long long)D_ * DI_];

// ---------------------------------------------------------------------------
// Helpers
// ---------------------------------------------------------------------------
__device__ __forceinline__ float sigmoidf_(float x) { return 1.f / (1.f + expf(-x)); }

__device__ __forceinline__ void splitstore2(fp16* H, fp16* L, long long idx,
                                            float v0, float v1)
{
    __half2 h = __floats2half2_rn(v0, v1);
    float h0 = __half2float(__low2half(h)), h1 = __half2float(__high2half(h));
    __half2 l = __floats2half2_rn(v0 - h0, v1 - h1);
    *(__half2*)(H + idx) = h;
    *(__half2*)(L + idx) = l;
}

__device__ __forceinline__ void store_planes4(fp16* H, fp16* L, long long idx, float4 v)
{
    __half2 h01 = __floats2half2_rn(v.x, v.y);
    __half2 h23 = __floats2half2_rn(v.z, v.w);
    float h0f = __half2float(__low2half(h01)),  h1f = __half2float(__high2half(h01));
    float h2f = __half2float(__low2half(h23)),  h3f = __half2float(__high2half(h23));
    __half2 l01 = __floats2half2_rn(v.x - h0f, v.y - h1f);
    __half2 l23 = __floats2half2_rn(v.z - h2f, v.w - h3f);
    ((__half2*)(H + idx))[0] = h01; ((__half2*)(H + idx))[1] = h23;
    ((__half2*)(L + idx))[0] = l01; ((__half2*)(L + idx))[1] = l23;
}

__device__ __forceinline__ uint32_t smem_u32(const void* p)
{
    uint32_t a;
    asm("{ .reg .u64 t; cvta.to.shared.u64 t, %1; cvt.u32.u64 %0, t; }" : "=r"(a) : "l"(p));
    return a;
}
__device__ __forceinline__ void cp16(uint32_t s, const void* g)
{
    asm volatile("cp.async.cg.shared.global [%0], [%1], 16;" :: "r"(s), "l"(g));
}
__device__ __forceinline__ void ldsm4(uint32_t* r, uint32_t addr)
{
    asm volatile("ldmatrix.sync.aligned.m8n8.x4.shared.b16 {%0,%1,%2,%3}, [%4];"
                 : "=r"(r[0]), "=r"(r[1]), "=r"(r[2]), "=r"(r[3]) : "r"(addr));
}
__device__ __forceinline__ void mma16816(float* c, const uint32_t* a,
                                         uint32_t b0, uint32_t b1)
{
    asm volatile(
        "mma.sync.aligned.m16n8k16.row.col.f32.f16.f16.f32 "
        "{%0,%1,%2,%3},{%4,%5,%6,%7},{%8,%9},{%0,%1,%2,%3};"
        : "+f"(c[0]), "+f"(c[1]), "+f"(c[2]), "+f"(c[3])
        : "r"(a[0]), "r"(a[1]), "r"(a[2]), "r"(a[3]), "r"(b0), "r"(b1));
}

#define EF32    0
#define ERKV    3   /* planes, sigmoid(E1)*(acc+bias+E0)  */
#define EADD    4   /* f32, acc+E0                        */
#define ECMFIN  5   /* f32, E0 + sigmoid(E1)*acc          */
#define EMEGA1  7   /* z=0: qk planes + Vsa; z=1,2: v,r into Cf2 */
#define EMEGA2  8   /* z<4: kc relu^2 planes; z=4: r2 f32 */

// ---------------------------------------------------------------------------
// fp16 split NT GEMM on mma.sync, 3-pass: C = Ah*Bh + Al*Bh + Ah*Bl.
// Gated jobs (r in MEGA1 z=2, r2 in MEGA2 z=4) drop the Ah*Bl pass:
// sigmoid-attenuated error (~2e-4 contribution) buys 1 fewer pass + plane.
// CTA 128x128, BK=32, 2-stage cp.async, 2 CTAs/SM.
// ---------------------------------------------------------------------------
#define ROWB   80
#define PLANE  (128 * ROWB)        /* 10240 B */
#define STAGEB (4 * PLANE)         /* 40960 B */

template<int EPI>
__global__ __launch_bounds__(256, 2)
void gemm_mma(const fp16* __restrict__ Ah, const fp16* __restrict__ Al, int lda,
              const fp16* __restrict__ Bh, const fp16* __restrict__ Bl, int ldb,
              const float* __restrict__ bias, const float* __restrict__ E0,
              const float* __restrict__ E1,
              float* __restrict__ Cf, fp16* __restrict__ Ch, fp16* __restrict__ Cl,
              int ldc, int K, float scale,
              long long sA, long long sB, long long sC,
              const fp16* __restrict__ A2h, const fp16* __restrict__ A2l,
              const fp16* __restrict__ B2h, const fp16* __restrict__ B2l,
              float* __restrict__ Cf2)
{
    extern __shared__ __align__(256) char smem[];

    // ---- job remap + gated-pass flag ----
    bool p3 = true;
    if (EPI == EMEGA1) {
        int z = blockIdx.z;
        if (z > 0) {
            if (blockIdx.x == 8) return;     // qk column block exists only for z=0
            Ah = A2h + (long long)(z - 1) * sA;
            Al = A2l + (long long)(z - 1) * sA;
            Bh = B2h + (long long)(z - 1) * sB;
            Bl = B2l + (long long)(z - 1) * sB;
            if (z == 2) p3 = false;          // r: sigmoid-gated
        }
    } else if (EPI == EMEGA2) {
        int z = blockIdx.z;
        if (z < 4) {
            Bh += (long long)z * 1024 * D_;
            Bl += (long long)z * 1024 * D_;
        } else {
            Ah = A2h; Al = A2l;
            Bh += (long long)4096 * D_;
            Bl += (long long)4096 * D_;
            p3 = false;                      // r2: sigmoid-gated
        }
    } else {
        Ah += (long long)blockIdx.z * sA;  Al += (long long)blockIdx.z * sA;
        Bh += (long long)blockIdx.z * sB;  Bl += (long long)blockIdx.z * sB;
    }
    const long long zC = (EPI == EMEGA1 || EPI == EMEGA2)
                       ? 0 : (long long)blockIdx.z * sC;

    const int tid  = threadIdx.x;
    const int lane = tid & 31;
    const int wid  = tid >> 5;
    const int wm   = wid & 1;
    const int wn   = wid >> 1;
    const int row0 = blockIdx.y * 128;
    const int col0 = blockIdx.x * 128;

    const uint32_t sbase = smem_u32(smem);
    const int NC = K >> 5;

    float acc[4][4][4];
    #pragma unroll
    for (int mf = 0; mf < 4; mf++)
        #pragma unroll
        for (int nf = 0; nf < 4; nf++)
            #pragma unroll
            for (int e = 0; e < 4; e++) acc[mf][nf][e] = 0.f;

    auto load_stage = [&](int c, int s) {
        uint32_t st = sbase + s * STAGEB;
        int k0 = c << 5;
        const fp16* srcs[4] = { Ah, Al, Bh, Bl };
        #pragma unroll
        for (int p = 0; p < 4; p++) {
            if (p == 3 && !p3) break;        // gated jobs skip the Bl plane
            int base = (p < 2) ? row0 : col0;
            int ld   = (p < 2) ? lda : ldb;
            const fp16* sp = srcs[p] + (long long)base * ld + k0;
            uint32_t db = st + p * PLANE;
            #pragma unroll
            for (int i = tid; i < 512; i += 256) {
                int rr = i >> 2, ch = i & 3;
                cp16(db + rr * ROWB + ch * 16, sp + (long long)rr * ld + ch * 8);
            }
        }
        asm volatile("cp.async.commit_group;" ::: "memory");
    };

    auto load_frags = [&](uint32_t st, int kk,
                          uint32_t (&aH)[4][4], uint32_t (&aL)[4][4],
                          uint32_t (&bH)[2][4], uint32_t (&bL)[2][4]) {
        int chunk = (kk * 2 + (lane >> 4)) * 16;
        int arow  = wm * 64 + (lane & 15);
        #pragma unroll
        for (int mf = 0; mf < 4; mf++) {
            uint32_t off = (uint32_t)(arow + mf * 16) * ROWB + chunk;
            ldsm4(aH[mf], st + off);
            ldsm4(aL[mf], st + PLANE + off);
        }
        int brow = wn * 32 + (lane & 7) + ((lane >> 3) & 1) * 8;
        #pragma unroll
        for (int np = 0; np < 2; np++) {
            uint32_t off = (uint32_t)(brow + np * 16) * ROWB + chunk;
            ldsm4(bH[np], st + 2 * PLANE + off);
            if (p3) ldsm4(bL[np], st + 3 * PLANE + off);
        }
    };

    auto do_mma = [&](uint32_t (&aH)[4][4], uint32_t (&aL)[4][4],
                      uint32_t (&bH)[2][4], uint32_t (&bL)[2][4]) {
        #pragma unroll
        for (int mf = 0; mf < 4; mf++)
            #pragma unroll
            for (int nf = 0; nf < 4; nf++) {
                int np = nf >> 1, sl = nf & 1;
                mma16816(acc[mf][nf], aH[mf], bH[np][sl], bH[np][2 + sl]);
            }
        #pragma unroll
        for (int mf = 0; mf < 4; mf++)
            #pragma unroll
            for (int nf = 0; nf < 4; nf++) {
                int np = nf >> 1, sl = nf & 1;
                mma16816(acc[mf][nf], aL[mf], bH[np][sl], bH[np][2 + sl]);
            }
        if (p3) {
            #pragma unroll
            for (int mf = 0; mf < 4; mf++)
                #pragma unroll
                for (int nf = 0; nf < 4; nf++) {
                    int np = nf >> 1, sl = nf & 1;
                    mma16816(acc[mf][nf], aH[mf], bL[np][sl], bL[np][2 + sl]);
                }
        }
    };

    load_stage(0, 0);
    if (NC > 1) load_stage(1, 1);

    for (int c = 0; c < NC; c++) {
        int s = c & 1;
        if (c + 1 < NC) asm volatile("cp.async.wait_group 1;" ::: "memory");
        else            asm volatile("cp.async.wait_group 0;" ::: "memory");
        __syncthreads();
        uint32_t st = sbase + s * STAGEB;

        uint32_t aH[4][4], aL[4][4], bH[2][4], bL[2][4];
        load_frags(st, 0, aH, aL, bH, bL);
        do_mma(aH, aL, bH, bL);

        load_frags(st, 1, aH, aL, bH, bL);
        __syncthreads();
        if (c + 2 < NC) load_stage(c + 2, s);
        do_mma(aH, aL, bH, bL);
    }

    // ---- epilogue ----
    #pragma unroll
    for (int mf = 0; mf < 4; mf++) {
        #pragma unroll
        for (int nf = 0; nf < 4; nf++) {
            int rA = row0 + wm * 64 + mf * 16 + (lane >> 2);
            int cB = col0 + wn * 32 + nf * 8 + (lane & 3) * 2;
            #pragma unroll
            for (int h = 0; h < 2; h++) {
                int rr = rA + h * 8;
                long long idx = (long long)rr * ldc + cB + zC;
                float v0 = acc[mf][nf][h * 2 + 0];
                float v1 = acc[mf][nf][h * 2 + 1];
                if (EPI == EF32) {
                    *(float2*)(Cf + idx) = make_float2(v0 * scale, v1 * scale);
                } else if (EPI == EMEGA1) {
                    if (blockIdx.z == 0) {
                        if (col0 < 128) {
                            long long qi = (long long)rr * 128 + cB;
                            splitstore2(Ch, Cl, qi, v0 + bias[cB], v1 + bias[cB + 1]);
                        } else {
                            long long vi = (long long)rr * 1024 + (cB - 128);
                            *(float2*)(Cf + vi) =
                                make_float2(v0 + bias[cB], v1 + bias[cB + 1]);
                        }
                    } else {
                        long long o = (long long)(blockIdx.z - 1) * ((long long)N_ * D_)
                                    + (long long)rr * 1024 + cB;
                        *(float2*)(Cf2 + o) = make_float2(v0, v1);
                    }
                } else if (EPI == EMEGA2) {
                    if (blockIdx.z < 4) {
                        long long ki = (long long)rr * 4096
                                     + (long long)blockIdx.z * 1024 + cB;
                        float u0 = fmaxf(v0, 0.f), u1 = fmaxf(v1, 0.f);
                        splitstore2(Ch, Cl, ki, u0 * u0, u1 * u1);
                    } else {
                        *(float2*)(Cf + (long long)rr * 1024 + cB) =
                            make_float2(v0, v1);
                    }
                } else if (EPI == ERKV) {
                    float o0 = sigmoidf_(E1[idx]) * (v0 + bias[cB] + E0[idx]);
                    float o1 = sigmoidf_(E1[idx + 1]) * (v1 + bias[cB + 1] + E0[idx + 1]);
                    splitstore2(Ch, Cl, idx, o0, o1);
                } else if (EPI == EADD) {
                    *(float2*)(Cf + idx) = make_float2(v0 + E0[idx], v1 + E0[idx + 1]);
                } else { // ECMFIN
                    float o0 = E0[idx]     + sigmoidf_(E1[idx])     * v0;
                    float o1 = E0[idx + 1] + sigmoidf_(E1[idx + 1]) * v1;
                    *(float2*)(Cf + idx) = make_float2(o0, o1);
                }
            }
        }
    }
}

// ---------------------------------------------------------------------------
// Weight prep: hi/lo fp16 planes + packing, one launch.
// ---------------------------------------------------------------------------
__global__ __launch_bounds__(256)
void split_all_kernel(const float* tmv, const float* tmr, const float* qw,
                      const float* kw,  const float* svw, const float* ow,
                      const float* tow, const float* crw, const float* ckw,
                      const float* cvw,
                      const float* qb, const float* kb, const float* svb,
                      float* bias)
{
    const long long t0 = blockIdx.x * 256 + threadIdx.x;
    const long long st = (long long)gridDim.x * 256;
    const int DD4 = D_ * D_ / 4;

    if (blockIdx.x == 0)
        for (int t = threadIdx.x; t < 1152; t += 256)
            bias[t] = (t < 64) ? qb[t] : (t < 128) ? kb[t - 64] : svb[t - 128];

    for (long long i = t0; i < DD4; i += st)
        store_planes4(g_wvrh, g_wvrl, i * 4, ((const float4*)tmv)[i]);
    for (long long i = t0; i < DD4; i += st)
        store_planes4(g_wvrh + D_*D_, g_wvrl + D_*D_, i * 4, ((const float4*)tmr)[i]);
    for (long long i = t0; i < 1152 * 256; i += st) {
        int row = (int)(i >> 8), c = (int)(i & 255);
        const float* src = (row < 64)  ? qw  + (long long)row * 1024
                         : (row < 128) ? kw  + (long long)(row - 64) * 1024
                                       : svw + (long long)(row - 128) * 1024;
        store_planes4(g_wqksvh, g_wqksvl, i * 4, ((const float4*)src)[c]);
    }
    for (long long i = t0; i < DD4; i += st)
        store_planes4(g_woh,  g_wol,  i * 4, ((const float4*)ow)[i]);
    for (long long i = t0; i < DD4; i += st)
        store_planes4(g_wtoh, g_wtol, i * 4, ((const float4*)tow)[i]);
    for (long long i = t0; i < 5120 * 256; i += st) {
        int row = (int)(i >> 8), c = (int)(i & 255);
        const float* src = (row < 4096) ? ckw + (long long)row * 1024
                                        : crw + (long long)(row - 4096) * 1024;
        store_planes4(g_wckcrh, g_wckcrl, i * 4, ((const float4*)src)[c]);
    }
    for (long long i = t0; i < (long long)D_ * DI_ / 4; i += st)
        store_planes4(g_wcvh, g_wcvl, i * 4, ((const float4*)cvw)[i]);
}

// ---------------------------------------------------------------------------
// Fused RMSNorm + token-shift mix
// ---------------------------------------------------------------------------
__global__ __launch_bounds__(256)
void normmix_kernel(const float* __restrict__ x, const float* __restrict__ nw,
                    const float* __restrict__ mA, const float* __restrict__ mB,
                    fp16* __restrict__ x1h, fp16* __restrict__ x1l,
                    fp16* __restrict__ ah, fp16* __restrict__ al,
                    fp16* __restrict__ bh, fp16* __restrict__ bl)
{
    int n = blockIdx.x, tid = threadIdx.x;
    int prev = ((n & (S_ - 1)) == 0) ? n : n - 1;
    float4 xv = ((const float4*)(x + (long long)n    * D_))[tid];
    float4 pv = ((const float4*)(x + (long long)prev * D_))[tid];
    float ssn = xv.x*xv.x + xv.y*xv.y + xv.z*xv.z + xv.w*xv.w;
    float ssp = pv.x*pv.x + pv.y*pv.y + pv.z*pv.z + pv.w*pv.w;
    #pragma unroll
    for (int off = 16; off; off >>= 1) {
        ssn += __shfl_xor_sync(~0u, ssn, off);
        ssp += __shfl_xor_sync(~0u, ssp, off);
    }
    __shared__ float wn_[8], wp_[8];
    __shared__ float s_sn, s_sp;
    if ((tid & 31) == 0) { wn_[tid >> 5] = ssn; wp_[tid >> 5] = ssp; }
    __syncthreads();
    if (tid == 0) {
        float tn = 0.f, tp = 0.f;
        #pragma unroll
        for (int i = 0; i < 8; i++) { tn += wn_[i]; tp += wp_[i]; }
        s_sn = 1.f / (sqrtf(tn / (float)D_) + 1e-8f);
        s_sp = 1.f / (sqrtf(tp / (float)D_) + 1e-8f);
    }
    __syncthreads();
    float scn = s_sn, scp = s_sp;
    float4 wv = ((const float4*)nw)[tid];
    float4 xn = make_float4(xv.x*wv.x*scn, xv.y*wv.y*scn, xv.z*wv.z*scn, xv.w*wv.w*scn);
    float4 xp = make_float4(pv.x*wv.x*scp, pv.y*wv.y*scp, pv.z*wv.z*scp, pv.w*wv.w*scp);
    long long idx = (long long)n * D_ + tid * 4;
    if (x1h) store_planes4(x1h, x1l, idx, xn);
    float4 ma = ((const float4*)mA)[tid];
    float4 mb = ((const float4*)mB)[tid];
    float4 oa = make_float4(xn.x*ma.x + xp.x*(1.f-ma.x), xn.y*ma.y + xp.y*(1.f-ma.y),
                            xn.z*ma.z + xp.z*(1.f-ma.z), xn.w*ma.w + xp.w*(1.f-ma.w));
    float4 ob = make_float4(xn.x*mb.x + xp.x*(1.f-mb.x), xn.y*mb.y + xp.y*(1.f-mb.y),
                            xn.z*mb.z + xp.z*(1.f-mb.z), xn.w*mb.w + xp.w*(1.f-mb.w));
    store_planes4(ah, al, idx, oa);
    store_planes4(bh, bl, idx, ob);
}

// ---------------------------------------------------------------------------
// Top-k(32) + softmax + sparse V gather -> fp16 planes
// ---------------------------------------------------------------------------
__global__ __launch_bounds__(256)
void topk_attn_kernel(const float* __restrict__ scores, const float* __restrict__ V,
                      fp16* __restrict__ oh, fp16* __restrict__ ol)
{
    int q = blockIdx.x, b = q >> 12, qs = q & (S_ - 1), tid = threadIdx.x;
    const float* srow = scores + (long long)b * S_ * S_ + (long long)qs * S_;
    float s[16];
    #pragma unroll
    for (int i = 0; i < 16; i++) s[i] = srow[i * 256 + tid];

    __shared__ float wv[8]; __shared__ int wi[8];
    __shared__ float top_val[TOPK_]; __shared__ int top_idx[TOPK_];
    __shared__ int s_win;
    const float NEG = -__int_as_float(0x7f800000);

    for (int t = 0; t < TOPK_; t++) {
        float best = NEG; int bi = 0;
        #pragma unroll
        for (int i = 0; i < 16; i++) if (s[i] > best) { best = s[i]; bi = i; }
        int gidx = bi * 256 + tid;
        #pragma unroll
        for (int off = 16; off; off >>= 1) {
            float ov = __shfl_down_sync(~0u, best, off);
            int   oi = __shfl_down_sync(~0u, gidx, off);
            if (ov > best) { best = ov; gidx = oi; }
        }
        if ((tid & 31) == 0) { wv[tid >> 5] = best; wi[tid >> 5] = gidx; }
        __syncthreads();
        if (tid == 0) {
            float bb = wv[0]; int bbi = wi[0];
            #pragma unroll
            for (int w = 1; w < 8; w++) if (wv[w] > bb) { bb = wv[w]; bbi = wi[w]; }
            top_val[t] = bb; top_idx[t] = bbi; s_win = bbi;
        }
        __syncthreads();
        int win = s_win;
        if ((win & 255) == tid) s[win >> 8] = NEG;
    }

    __shared__ float wts[TOPK_];
    if (tid < 32) {
        float e = expf(top_val[tid] - top_val[0]);
        float ssum = e;
        #pragma unroll
        for (int off = 16; off; off >>= 1) ssum += __shfl_xor_sync(~0u, ssum, off);
        wts[tid] = e / ssum;
    }
    __syncthreads();

    const float* Vb = V + (long long)b * S_ * D_;
    float4 acc = make_float4(0.f, 0.f, 0.f, 0.f);
    #pragma unroll
    for (int t = 0; t < TOPK_; t++) {
        float w = wts[t];
        float4 vr = *(const float4*)&Vb[(long long)top_idx[t] * D_ + tid * 4];
        acc.x += w*vr.x; acc.y += w*vr.y; acc.z += w*vr.z; acc.w += w*vr.w;
    }
    store_planes4(oh, ol, (long long)q * D_ + tid * 4, acc);
}

// ---------------------------------------------------------------------------
// Host
// ---------------------------------------------------------------------------
template <typename T> static void* symaddr(T& sym)
{ void* p = nullptr; cudaGetSymbolAddress(&p, sym); return p; }

extern "C" void kernel_launch(void* const* d_in, const int* in_sizes, int n_in,
                              void* d_out, int out_size)
{
    const float* x        = (const float*)d_in[0];
    const float* norm1_w  = (const float*)d_in[1];
    const float* tm_mix_v = (const float*)d_in[3];
    const float* tm_mix_r = (const float*)d_in[4];
    const float* tm_value_w  = (const float*)d_in[6];
    const float* tm_recept_w = (const float*)d_in[7];
    const float* tm_out_w = (const float*)d_in[8];
    const float* sa_q_w   = (const float*)d_in[9];
    const float* sa_q_b   = (const float*)d_in[10];
    const float* sa_k_w   = (const float*)d_in[11];
    const float* sa_k_b   = (const float*)d_in[12];
    const float* sa_v_w   = (const float*)d_in[13];
    const float* sa_v_b   = (const float*)d_in[14];
    const float* sa_o_w   = (const float*)d_in[15];
    const float* sa_o_b   = (const float*)d_in[16];
    const float* norm2_w  = (const float*)d_in[17];
    const float* cm_mix_k = (const float*)d_in[18];
    const float* cm_mix_r = (const float*)d_in[19];
    const float* cm_key_w = (const float*)d_in[20];
    const float* cm_recept_w = (const float*)d_in[21];
    const float* cm_value_w  = (const float*)d_in[22];
    float* out = (float*)d_out;

    float* vr   = (float*)symaddr(g_vr);
    float* Vsa  = (float*)symaddr(g_Vsa);
    float* sc   = (float*)symaddr(g_scores);
    float* xmid = (float*)symaddr(g_xmid);
    float* r2   = (float*)symaddr(g_r2);
    float* bias = (float*)symaddr(g_bias);

    fp16 *x1h=(fp16*)symaddr(g_x1h),   *x1l=(fp16*)symaddr(g_x1l);
    fp16 *xabh=(fp16*)symaddr(g_xabh), *xabl=(fp16*)symaddr(g_xabl);
    fp16 *qkh=(fp16*)symaddr(g_qkh),   *qkl=(fp16*)symaddr(g_qkl);
    fp16 *aph=(fp16*)symaddr(g_aph),   *apl=(fp16*)symaddr(g_apl);
    fp16 *rkh=(fp16*)symaddr(g_rkh),   *rkl=(fp16*)symaddr(g_rkl);
    fp16 *kch=(fp16*)symaddr(g_kch),   *kcl=(fp16*)symaddr(g_kcl);
    fp16 *wvrh=(fp16*)symaddr(g_wvrh),     *wvrl=(fp16*)symaddr(g_wvrl);
    fp16 *wqksvh=(fp16*)symaddr(g_wqksvh), *wqksvl=(fp16*)symaddr(g_wqksvl);
    fp16 *woh=(fp16*)symaddr(g_woh),   *wol=(fp16*)symaddr(g_wol);
    fp16 *wtoh=(fp16*)symaddr(g_wtoh), *wtol=(fp16*)symaddr(g_wtol);
    fp16 *wckcrh=(fp16*)symaddr(g_wckcrh), *wckcrl=(fp16*)symaddr(g_wckcrl);
    fp16 *wcvh=(fp16*)symaddr(g_wcvh), *wcvl=(fp16*)symaddr(g_wcvl);

    const int SMB = 2 * STAGEB;   // 81920 -> 2 CTAs/SM
    cudaFuncSetAttribute(gemm_mma<EF32>,   cudaFuncAttributeMaxDynamicSharedMemorySize, SMB);
    cudaFuncSetAttribute(gemm_mma<ERKV>,   cudaFuncAttributeMaxDynamicSharedMemorySize, SMB);
    cudaFuncSetAttribute(gemm_mma<EADD>,   cudaFuncAttributeMaxDynamicSharedMemorySize, SMB);
    cudaFuncSetAttribute(gemm_mma<ECMFIN>, cudaFuncAttributeMaxDynamicSharedMemorySize, SMB);
    cudaFuncSetAttribute(gemm_mma<EMEGA1>, cudaFuncAttributeMaxDynamicSharedMemorySize, SMB);
    cudaFuncSetAttribute(gemm_mma<EMEGA2>, cudaFuncAttributeMaxDynamicSharedMemorySize, SMB);

    // 0: weight prep
    split_all_kernel<<<2048, 256>>>(tm_value_w, tm_recept_w, sa_q_w, sa_k_w,
                                    sa_v_w, sa_o_w, tm_out_w, cm_recept_w,
                                    cm_key_w, cm_value_w,
                                    sa_q_b, sa_k_b, sa_v_b, bias);

    // 1: fused norm1 + mix1
    normmix_kernel<<<N_, 256>>>(x, norm1_w, tm_mix_v, tm_mix_r,
                                x1h, x1l,
                                xabh, xabl, xabh + (long long)N_*D_, xabl + (long long)N_*D_);

    // 2: MEGA1 — z=0: x1@[qk;sv]; z=1: xa@wv -> v; z=2 (2-pass): xb@wr -> r
    gemm_mma<EMEGA1><<<dim3(9,64,3), 256, SMB>>>(
        x1h, x1l, D_, wqksvh, wqksvl, D_,
        bias, nullptr, nullptr,
        Vsa, qkh, qkl, 1152, D_, 1.f,
        (long long)N_*D_, (long long)D_*D_, 0,
        xabh, xabl, wvrh, wvrl, vr);

    // 3: scores = Q @ K^T / 8
    gemm_mma<EF32><<<dim3(32,32,2), 256, SMB>>>(qkh, qkl, 128, qkh + 64, qkl + 64, 128,
        nullptr, nullptr, nullptr, sc, nullptr, nullptr, S_, 64, 0.125f,
        (long long)S_*128, (long long)S_*128, (long long)S_*S_,
        nullptr, nullptr, nullptr, nullptr, nullptr);

    // 4: topk + softmax + gather
    topk_attn_kernel<<<N_, 256>>>(sc, Vsa, aph, apl);

    // 5: rkv = sigmoid(r)*(ap@o_w^T + o_b + v)
    gemm_mma<ERKV><<<dim3(8,64,1), 256, SMB>>>(aph, apl, D_, woh, wol, D_,
        sa_o_b, vr, vr + (long long)N_*D_, nullptr, rkh, rkl, D_, D_, 1.f, 0, 0, 0,
        nullptr, nullptr, nullptr, nullptr, nullptr);
    // 6: xmid = x + rkv@tm_out^T
    gemm_mma<EADD><<<dim3(8,64,1), 256, SMB>>>(rkh, rkl, D_, wtoh, wtol, D_,
        nullptr, x, nullptr, xmid, nullptr, nullptr, D_, D_, 1.f, 0, 0, 0,
        nullptr, nullptr, nullptr, nullptr, nullptr);

    // 7: fused norm2 + mix2
    normmix_kernel<<<N_, 256>>>(xmid, norm2_w, cm_mix_k, cm_mix_r,
                                nullptr, nullptr,
                                xabh, xabl, xabh + (long long)N_*D_, xabl + (long long)N_*D_);

    // 8: MEGA2 — z<4: kc slabs; z=4 (2-pass): r2 = xb@cr^T
    gemm_mma<EMEGA2><<<dim3(8,64,5), 256, SMB>>>(
        xabh, xabl, D_, wckcrh, wckcrl, D_,
        nullptr, nullptr, nullptr,
        r2, kch, kcl, DI_, D_, 1.f,
        0, 0, 0,
        xabh + (long long)N_*D_, xabl + (long long)N_*D_, nullptr, nullptr, nullptr);

    // 9: out = xmid + sigmoid(r2)*(kc@cv^T)
    gemm_mma<ECMFIN><<<dim3(8,64,1), 256, SMB>>>(kch, kcl, DI_, wcvh, wcvl, DI_,
        nullptr, xmid, r2, out, nullptr, nullptr, D_, DI_, 1.f, 0, 0, 0,
        nullptr, nullptr, nullptr, nullptr, nullptr);
}